// round 4
// baseline (speedup 1.0000x reference)
#include <cuda_runtime.h>
#include <cuda_bf16.h>

// Problem dims (fixed for this dataset)
#define BDIM 8
#define TDIM 2048
#define CDIM 1024
#define MTOT (BDIM * TDIM)          // 16384
#define ELEMS (MTOT * CDIM)         // 16,777,216

// ---------------------------------------------------------------------------
// Scratch (static device arrays — no allocation allowed)
// ---------------------------------------------------------------------------
__device__ float g_xk[ELEMS];   // mixed xk; later reused as rwkv = sigmoid(r)*wkv
__device__ float g_xv[ELEMS];   // mixed xv
__device__ float g_xr[ELEMS];   // mixed xr
__device__ float g_k [ELEMS];   // k = xk @ Wk
__device__ float g_v [ELEMS];   // v = xv @ Wv
__device__ float g_r [ELEMS];   // r_pre = xr @ Wr (pre-sigmoid)

// ---------------------------------------------------------------------------
// Kernel 1: token-shift mix (xk, xv, xr) + emit last_x
// ---------------------------------------------------------------------------
__global__ __launch_bounds__(256)
void mix_kernel(const float* __restrict__ x,
                const float* __restrict__ last_x,
                const float* __restrict__ tmk,
                const float* __restrict__ tmv,
                const float* __restrict__ tmr,
                float* __restrict__ out_lastx)
{
    int idx = blockIdx.x * 256 + threadIdx.x;
    if (idx >= ELEMS) return;
    int c = idx & (CDIM - 1);
    int m = idx >> 10;            // b*T + t
    int t = m & (TDIM - 1);
    int b = m >> 11;

    float xc = x[idx];
    float xp = (t == 0) ? last_x[b * CDIM + c] : x[idx - CDIM];

    float mk = tmk[c], mv = tmv[c], mr = tmr[c];
    // x*m + xp*(1-m) == xp + m*(x - xp)
    float d = xc - xp;
    g_xk[idx] = fmaf(mk, d, xp);
    g_xv[idx] = fmaf(mv, d, xp);
    g_xr[idx] = fmaf(mr, d, xp);

    if (t == TDIM - 1) out_lastx[b * CDIM + c] = xc;
}

// ---------------------------------------------------------------------------
// SGEMM core: C[M,N] = A[M,K] @ B[K,N]  (row-major, M%128==0, N%128==0,
// K%16==0). 128x128 tile, BK=16, 256 threads, 8x8 per thread.
// Double-buffered smem + global->register prefetch.
// Inner product uses packed fma.rn.f32x2 (FFMA2): 2 fp32 FMAs per issue
// slot; ptxas never emits this from C++ (SASS_QUICKREF pattern table).
// ---------------------------------------------------------------------------
#define BK 16

__device__ __forceinline__
void sgemm128_body(const float* __restrict__ A,
                   const float* __restrict__ B,
                   float* __restrict__ C,
                   int M, int N, int K,
                   int rowBase, int colBase)
{
    __shared__ float As[2][BK][128];
    __shared__ float Bs[2][BK][132];   // +4 pad; row stride 528B (8B aligned)

    const int tid = threadIdx.x;
    const int tx  = tid & 15;          // 0..15 (cols)
    const int ty  = tid >> 4;          // 0..15 (rows)

    // A tile loader: 128 rows x 16 cols; 2 float4 per thread (8 consecutive)
    const int aRow = tid >> 1;         // 0..127
    const int aCol = (tid & 1) * 8;    // 0 or 8
    // B tile loader: 16 rows x 128 cols; 2 float4 per thread (rows r, r+8)
    const int bRow = tid >> 5;         // 0..7
    const int bCol = (tid & 31) * 4;   // 0..124

    const float* Aptr = A + (long)(rowBase + aRow) * K + aCol;
    const float* Bptr0 = B + (long)bRow * N + colBase + bCol;
    const float* Bptr1 = B + (long)(bRow + 8) * N + colBase + bCol;

    // 8x8 accumulator as 8x4 packed f32x2 pairs (pair along j)
    unsigned long long acc2[8][4];
    #pragma unroll
    for (int i = 0; i < 8; i++)
        #pragma unroll
        for (int jp = 0; jp < 4; jp++) acc2[i][jp] = 0ULL;

    // prime buffer 0
    {
        float4 av0 = *reinterpret_cast<const float4*>(Aptr);
        float4 av1 = *reinterpret_cast<const float4*>(Aptr + 4);
        float4 bv0 = *reinterpret_cast<const float4*>(Bptr0);
        float4 bv1 = *reinterpret_cast<const float4*>(Bptr1);
        As[0][aCol + 0][aRow] = av0.x;
        As[0][aCol + 1][aRow] = av0.y;
        As[0][aCol + 2][aRow] = av0.z;
        As[0][aCol + 3][aRow] = av0.w;
        As[0][aCol + 4][aRow] = av1.x;
        As[0][aCol + 5][aRow] = av1.y;
        As[0][aCol + 6][aRow] = av1.z;
        As[0][aCol + 7][aRow] = av1.w;
        *reinterpret_cast<float4*>(&Bs[0][bRow    ][bCol]) = bv0;
        *reinterpret_cast<float4*>(&Bs[0][bRow + 8][bCol]) = bv1;
    }
    __syncthreads();

    int buf = 0;
    for (int k0 = 0; k0 < K; k0 += BK, buf ^= 1) {
        float4 av0, av1, bv0, bv1;
        const bool more = (k0 + BK) < K;
        if (more) {
            av0 = *reinterpret_cast<const float4*>(Aptr + (k0 + BK));
            av1 = *reinterpret_cast<const float4*>(Aptr + (k0 + BK) + 4);
            bv0 = *reinterpret_cast<const float4*>(Bptr0 + (long)(k0 + BK) * N);
            bv1 = *reinterpret_cast<const float4*>(Bptr1 + (long)(k0 + BK) * N);
        }

        #pragma unroll
        for (int kk = 0; kk < BK; kk++) {
            // b pairs: 4 x LDS.64 (Bs row base + tx*8 is 8B aligned)
            unsigned long long b2[4];
            #pragma unroll
            for (int jp = 0; jp < 4; jp++)
                b2[jp] = *reinterpret_cast<const unsigned long long*>(
                             &Bs[buf][kk][tx * 8 + jp * 2]);
            #pragma unroll
            for (int i = 0; i < 8; i++) {
                unsigned int au = __float_as_uint(As[buf][kk][ty * 8 + i]);
                unsigned long long a2;
                asm("mov.b64 %0, {%1, %1};" : "=l"(a2) : "r"(au));
                #pragma unroll
                for (int jp = 0; jp < 4; jp++)
                    asm("fma.rn.f32x2 %0, %1, %2, %0;"
                        : "+l"(acc2[i][jp]) : "l"(a2), "l"(b2[jp]));
            }
        }

        if (more) {
            int nb = buf ^ 1;
            As[nb][aCol + 0][aRow] = av0.x;
            As[nb][aCol + 1][aRow] = av0.y;
            As[nb][aCol + 2][aRow] = av0.z;
            As[nb][aCol + 3][aRow] = av0.w;
            As[nb][aCol + 4][aRow] = av1.x;
            As[nb][aCol + 5][aRow] = av1.y;
            As[nb][aCol + 6][aRow] = av1.z;
            As[nb][aCol + 7][aRow] = av1.w;
            *reinterpret_cast<float4*>(&Bs[nb][bRow    ][bCol]) = bv0;
            *reinterpret_cast<float4*>(&Bs[nb][bRow + 8][bCol]) = bv1;
            __syncthreads();
        }
    }

    // Epilogue: each packed pair is (c[j], c[j+1]) with low word = lower col.
    #pragma unroll
    for (int i = 0; i < 8; i++) {
        float* Crow = C + (long)(rowBase + ty * 8 + i) * N + colBase + tx * 8;
        #pragma unroll
        for (int jp = 0; jp < 4; jp++)
            *reinterpret_cast<unsigned long long*>(Crow + jp * 2) = acc2[i][jp];
    }
}

// Single GEMM launch (used for the output projection)
__global__ __launch_bounds__(256)
void sgemm128(const float* __restrict__ A,
              const float* __restrict__ B,
              float* __restrict__ C,
              int M, int N, int K)
{
    sgemm128_body(A, B, C, M, N, K, blockIdx.y * 128, blockIdx.x * 128);
}

// Batched 3-GEMM launch: blockIdx.z picks (A, W, C) triple. One big grid ->
// single tail instead of three.
__global__ __launch_bounds__(256)
void sgemm128_x3(const float* __restrict__ A0, const float* __restrict__ W0, float* __restrict__ C0,
                 const float* __restrict__ A1, const float* __restrict__ W1, float* __restrict__ C1,
                 const float* __restrict__ A2, const float* __restrict__ W2, float* __restrict__ C2,
                 int M, int N, int K)
{
    const float* A; const float* W; float* C;
    if (blockIdx.z == 0)      { A = A0; W = W0; C = C0; }
    else if (blockIdx.z == 1) { A = A1; W = W1; C = C1; }
    else                      { A = A2; W = W2; C = C2; }
    sgemm128_body(A, W, C, M, N, K, blockIdx.y * 128, blockIdx.x * 128);
}

// ---------------------------------------------------------------------------
// Kernel 3: WKV scan over T (one thread per (b,c) channel), fused with
// rwkv = sigmoid(r_pre) * wkv written into g_xk. Emits final aa/bb/pp.
// ---------------------------------------------------------------------------
__global__ __launch_bounds__(256)
void wkv_scan_kernel(const float* __restrict__ aa_in,
                     const float* __restrict__ bb_in,
                     const float* __restrict__ pp_in,
                     const float* __restrict__ time_first,
                     const float* __restrict__ time_decay,
                     float* __restrict__ aa_out,
                     float* __restrict__ bb_out,
                     float* __restrict__ pp_out)
{
    int g = blockIdx.x * 256 + threadIdx.x;       // 0 .. B*C-1
    if (g >= BDIM * CDIM) return;
    int b = g >> 10;
    int c = g & (CDIM - 1);

    float aa = aa_in[g], bb = bb_in[g], pp = pp_in[g];
    const float tf = time_first[c];
    const float td = time_decay[c];

    const long base = (long)b * TDIM * CDIM + c;
    const float* kp = g_k + base;
    const float* vp = g_v + base;
    const float* rp = g_r + base;
    float*       op = g_xk + base;   // rwkv output (reuses xk scratch)

    for (int t = 0; t < TDIM; t++) {
        long off = (long)t * CDIM;
        float kt = kp[off];
        float vt = vp[off];
        float rt = rp[off];

        float ww = tf + kt;
        float qq = fmaxf(pp, ww);
        float e1 = __expf(pp - qq);
        float e2 = __expf(ww - qq);
        float wkv = (e1 * aa + e2 * vt) / (e1 * bb + e2);

        float sig = 1.0f / (1.0f + __expf(-rt));
        op[off] = sig * wkv;

        float ww2 = pp + td;
        float qq2 = fmaxf(ww2, kt);
        float e1b = __expf(ww2 - qq2);
        float e2b = __expf(kt - qq2);
        aa = e1b * aa + e2b * vt;
        bb = e1b * bb + e2b;
        pp = qq2;
    }

    aa_out[g] = aa;
    bb_out[g] = bb;
    pp_out[g] = pp;
}

// ---------------------------------------------------------------------------
// Launch
// ---------------------------------------------------------------------------
extern "C" void kernel_launch(void* const* d_in, const int* in_sizes, int n_in,
                              void* d_out, int out_size)
{
    const float* x       = (const float*)d_in[0];
    const float* last_x  = (const float*)d_in[1];
    const float* aa      = (const float*)d_in[2];
    const float* bb      = (const float*)d_in[3];
    const float* pp      = (const float*)d_in[4];
    const float* tmk     = (const float*)d_in[5];
    const float* tmv     = (const float*)d_in[6];
    const float* tmr     = (const float*)d_in[7];
    const float* tfirst  = (const float*)d_in[8];
    const float* tdecay  = (const float*)d_in[9];
    const float* Wk      = (const float*)d_in[10];
    const float* Wv      = (const float*)d_in[11];
    const float* Wr      = (const float*)d_in[12];
    const float* Wo      = (const float*)d_in[13];

    float* out       = (float*)d_out;
    float* out_lastx = out + (long)ELEMS;
    float* out_aa    = out_lastx + BDIM * CDIM;
    float* out_bb    = out_aa    + BDIM * CDIM;
    float* out_pp    = out_bb    + BDIM * CDIM;

    // Resolve scratch symbol addresses (host API, not a stream op — capture-safe)
    float *p_xk, *p_xv, *p_xr, *p_k, *p_v, *p_r;
    cudaGetSymbolAddress((void**)&p_xk, g_xk);
    cudaGetSymbolAddress((void**)&p_xv, g_xv);
    cudaGetSymbolAddress((void**)&p_xr, g_xr);
    cudaGetSymbolAddress((void**)&p_k,  g_k);
    cudaGetSymbolAddress((void**)&p_v,  g_v);
    cudaGetSymbolAddress((void**)&p_r,  g_r);

    // 1) token-shift mixes
    mix_kernel<<<ELEMS / 256, 256>>>(x, last_x, tmk, tmv, tmr, out_lastx);

    // 2) three projection GEMMs, one batched launch
    dim3 gemmGrid3(CDIM / 128, MTOT / 128, 3);   // (8, 128, 3)
    sgemm128_x3<<<gemmGrid3, 256>>>(p_xk, Wk, p_k,
                                    p_xv, Wv, p_v,
                                    p_xr, Wr, p_r,
                                    MTOT, CDIM, CDIM);

    // 3) WKV scan (+ fused sigmoid(r)*wkv -> g_xk)
    wkv_scan_kernel<<<(BDIM * CDIM) / 256, 256>>>(aa, bb, pp, tfirst, tdecay,
                                                  out_aa, out_bb, out_pp);

    // 4) output projection
    dim3 gemmGrid(CDIM / 128, MTOT / 128);
    sgemm128<<<gemmGrid, 256>>>(p_xk, Wo, out, MTOT, CDIM, CDIM);
}

// round 10
// speedup vs baseline: 2.3805x; 2.3805x over previous
#include <cuda_runtime.h>
#include <cuda_bf16.h>
#include <cstdint>

#define BDIM 8
#define TDIM 2048
#define CDIM 1024
#define MTOT (BDIM * TDIM)          // 16384
#define ELEMS (MTOT * CDIM)         // 16,777,216

// ---------------------------------------------------------------------------
// Scratch (static device arrays — no allocation allowed)
// ---------------------------------------------------------------------------
// bf16 hi/lo split activations: slot 0=xk (reused as rwkv), 1=xv, 2=xr
__device__ __align__(128) __nv_bfloat16 g_ahi[3L * ELEMS];
__device__ __align__(128) __nv_bfloat16 g_alo[3L * ELEMS];
// fp32 GEMM outputs: slot 0=k, 1=v, 2=r_pre
__device__ __align__(128) float g_kvr[3L * ELEMS];
// transposed bf16 hi/lo weights: slot 0=Wk,1=Wv,2=Wr,3=Wo ; layout [n][k]
__device__ __align__(128) __nv_bfloat16 g_wthi[4L * CDIM * CDIM];
__device__ __align__(128) __nv_bfloat16 g_wtlo[4L * CDIM * CDIM];

// ---------------------------------------------------------------------------
// PTX helpers — baseline sm_80+ ISA only (harness targets plain sm_103!)
// ---------------------------------------------------------------------------
__device__ __forceinline__ uint32_t smem_u32(const void* p) {
    uint32_t a;
    asm("{ .reg .u64 t; cvta.to.shared.u64 t, %1; cvt.u32.u64 %0, t; }"
        : "=r"(a) : "l"(p));
    return a;
}
__device__ __forceinline__ void cp16(uint32_t s, const void* g) {
    asm volatile("cp.async.cg.shared.global [%0], [%1], 16;"
                 :: "r"(s), "l"(g) : "memory");
}
#define CP_COMMIT() asm volatile("cp.async.commit_group;" ::: "memory")
#define CP_WAIT(n)  asm volatile("cp.async.wait_group %0;" :: "n"(n) : "memory")

__device__ __forceinline__ void ldsm4(uint32_t* r, uint32_t addr) {
    asm volatile("ldmatrix.sync.aligned.m8n8.x4.shared.b16 {%0,%1,%2,%3}, [%4];"
                 : "=r"(r[0]), "=r"(r[1]), "=r"(r[2]), "=r"(r[3]) : "r"(addr));
}
__device__ __forceinline__ void mma_bf16(float* d, const uint32_t* a,
                                         uint32_t b0, uint32_t b1) {
    asm volatile(
        "mma.sync.aligned.m16n8k16.row.col.f32.bf16.bf16.f32 "
        "{%0,%1,%2,%3}, {%4,%5,%6,%7}, {%8,%9}, {%0,%1,%2,%3};"
        : "+f"(d[0]), "+f"(d[1]), "+f"(d[2]), "+f"(d[3])
        : "r"(a[0]), "r"(a[1]), "r"(a[2]), "r"(a[3]), "r"(b0), "r"(b1));
}

// ---------------------------------------------------------------------------
// Kernel 1: token-shift mix -> hi/lo bf16 activation arrays + last_x
// ---------------------------------------------------------------------------
__device__ __forceinline__ void split_store(__nv_bfloat16* hi, __nv_bfloat16* lo,
                                            long idx, float v) {
    __nv_bfloat16 h = __float2bfloat16(v);
    float rem = v - __bfloat162float(h);
    hi[idx] = h;
    lo[idx] = __float2bfloat16(rem);
}

__global__ __launch_bounds__(256)
void mix_kernel(const float* __restrict__ x,
                const float* __restrict__ last_x,
                const float* __restrict__ tmk,
                const float* __restrict__ tmv,
                const float* __restrict__ tmr,
                float* __restrict__ out_lastx)
{
    long idx = (long)blockIdx.x * 256 + threadIdx.x;
    if (idx >= ELEMS) return;
    int c = (int)(idx & (CDIM - 1));
    long m = idx >> 10;
    int t = (int)(m & (TDIM - 1));
    int b = (int)(m >> 11);

    float xc = x[idx];
    float xp = (t == 0) ? last_x[b * CDIM + c] : x[idx - CDIM];
    float d = xc - xp;

    split_store(g_ahi + 0L * ELEMS, g_alo + 0L * ELEMS, idx, fmaf(tmk[c], d, xp));
    split_store(g_ahi + 1L * ELEMS, g_alo + 1L * ELEMS, idx, fmaf(tmv[c], d, xp));
    split_store(g_ahi + 2L * ELEMS, g_alo + 2L * ELEMS, idx, fmaf(tmr[c], d, xp));

    if (t == TDIM - 1) out_lastx[b * CDIM + c] = xc;
}

// ---------------------------------------------------------------------------
// Kernel 2: tiled weight transpose + hi/lo bf16 split. wt[n][k] = W[k][n].
// 32x32 smem tile; coalesced on both sides. Grid: (32 tiles n, 32 tiles k, 4).
// ---------------------------------------------------------------------------
__global__ __launch_bounds__(256)
void wconv_kernel(const float* __restrict__ W0, const float* __restrict__ W1,
                  const float* __restrict__ W2, const float* __restrict__ W3)
{
    __shared__ float tile[32][33];
    const int w = blockIdx.z;
    const float* W = (w == 0) ? W0 : (w == 1) ? W1 : (w == 2) ? W2 : W3;

    const int k0 = blockIdx.y * 32;
    const int n0 = blockIdx.x * 32;
    const int tx = threadIdx.x & 31;    // n within tile (load) / k (store)
    const int ty = threadIdx.x >> 5;    // 0..7

    // load 32x32 tile: rows k0+ty+8j, cols n0+tx (coalesced)
    #pragma unroll
    for (int j = 0; j < 4; j++) {
        int k = ty + j * 8;
        tile[k][tx] = W[(long)(k0 + k) * CDIM + n0 + tx];
    }
    __syncthreads();

    // store transposed: row n0+ty+8j, cols k0+tx (coalesced, 2B elems)
    long base = (long)w * CDIM * CDIM;
    #pragma unroll
    for (int j = 0; j < 4; j++) {
        int n = ty + j * 8;
        float v = tile[tx][n];
        long o = base + (long)(n0 + n) * CDIM + k0 + tx;
        __nv_bfloat16 h = __float2bfloat16(v);
        g_wthi[o] = h;
        g_wtlo[o] = __float2bfloat16(v - __bfloat162float(h));
    }
}

// ---------------------------------------------------------------------------
// Kernel 3: bf16 split GEMM via mma.sync (HMMA). C = (Ahi+Alo)@(Whi+Wlo)^T
//   A: [MTOT x 1024] bf16 row-major. W: [1024 x 1024] bf16 [n][k].
//   128x128 CTA tile, 8 warps (2m x 4n), 64x32 per warp. BK=32, 2-stage
//   cp.async pipeline. Smem rows padded to 80B (conflict-free ldmatrix).
//   3 accumulation passes: Ahi*Bhi + Ahi*Blo + Alo*Bhi.
// ---------------------------------------------------------------------------
#define BKG   32
#define TSTR  10240     // tile bytes: 128 rows x 80B stride
#define STAGE 40960     // 4 tiles per stage
#define GEMM_SMEM (2 * STAGE)   // 81920

__global__ __launch_bounds__(256, 1)
void gemm_mma(const __nv_bfloat16* __restrict__ AhiB,
              const __nv_bfloat16* __restrict__ AloB,
              const __nv_bfloat16* __restrict__ WhiB,
              const __nv_bfloat16* __restrict__ WloB,
              float* __restrict__ CB,
              long aStride, long wStride, long cStride)
{
    extern __shared__ char dynsmem[];
    const int z = blockIdx.z;
    const __nv_bfloat16* Ahi = AhiB + (long)z * aStride;
    const __nv_bfloat16* Alo = AloB + (long)z * aStride;
    const __nv_bfloat16* Whi = WhiB + (long)z * wStride;
    const __nv_bfloat16* Wlo = WloB + (long)z * wStride;
    float* C = CB + (long)z * cStride;

    const int tid  = threadIdx.x;
    const int wid  = tid >> 5;
    const int lane = tid & 31;
    const int rowBase = blockIdx.y * 128;
    const int colBase = blockIdx.x * 128;
    const int mBase = (wid >> 2) * 64;   // warpM in {0,1}
    const int nBase = (wid & 3) * 32;    // warpN in {0..3}

    const uint32_t sb = smem_u32(dynsmem);

    float acc[4][4][4];
    #pragma unroll
    for (int a = 0; a < 4; a++)
        #pragma unroll
        for (int b = 0; b < 4; b++)
            #pragma unroll
            for (int c = 0; c < 4; c++) acc[a][b][c] = 0.f;

    // ---- stage copy: 4 tiles x 512 16B-chunks = 2048 chunks; 8 per thread
    auto copyStage = [&](int stage, int kc) {
        uint32_t sbase = sb + stage * STAGE;
        #pragma unroll
        for (int j = 0; j < 8; j++) {
            int idx = j * 256 + tid;
            int tile = idx >> 9;         // 0..3
            int ci   = idx & 511;
            int row  = ci >> 2;          // 0..127
            int c4   = ci & 3;           // 16B chunk in row
            uint32_t soff = sbase + tile * TSTR + row * 80 + c4 * 16;
            const __nv_bfloat16* gp;
            if (tile == 0)      gp = Ahi + (long)(rowBase + row) * CDIM + kc + c4 * 8;
            else if (tile == 1) gp = Alo + (long)(rowBase + row) * CDIM + kc + c4 * 8;
            else if (tile == 2) gp = Whi + (long)(colBase + row) * CDIM + kc + c4 * 8;
            else                gp = Wlo + (long)(colBase + row) * CDIM + kc + c4 * 8;
            cp16(soff, gp);
        }
    };

    copyStage(0, 0);
    CP_COMMIT();

    const int S = CDIM / BKG;   // 32 steps
    const int sub = lane >> 3;
    const int r8  = lane & 7;

    for (int s = 0; s < S; s++) {
        if (s + 1 < S) { copyStage((s + 1) & 1, (s + 1) * BKG); CP_COMMIT(); CP_WAIT(1); }
        else           { CP_WAIT(0); }
        __syncthreads();

        uint32_t st   = sb + (s & 1) * STAGE;
        uint32_t aHiT = st;
        uint32_t aLoT = st + TSTR;
        uint32_t bHiT = st + 2 * TSTR;
        uint32_t bLoT = st + 3 * TSTR;

        #pragma unroll
        for (int k16 = 0; k16 < BKG; k16 += 16) {
            uint32_t ah[4][4], al[4][4], bh[2][4], bl[2][4];
            // A frags: lanes0-7 -> rows+0@k0, 8-15 -> rows+8@k0,
            //          16-23 -> rows+0@k8, 24-31 -> rows+8@k8
            #pragma unroll
            for (int mt = 0; mt < 4; mt++) {
                int arow = mBase + mt * 16 + (sub & 1) * 8 + r8;
                int kcol = k16 + (sub >> 1) * 8;
                uint32_t off = (uint32_t)(arow * 80 + kcol * 2);
                ldsm4(ah[mt], aHiT + off);
                ldsm4(al[mt], aLoT + off);
            }
            // B frags ([n][k] storage): lanes0-7 -> n+0@k0, 8-15 -> n+0@k8,
            //          16-23 -> n+8@k0, 24-31 -> n+8@k8
            #pragma unroll
            for (int nt = 0; nt < 2; nt++) {
                int brow = nBase + nt * 16 + (sub >> 1) * 8 + r8;
                int kcol = k16 + (sub & 1) * 8;
                uint32_t off = (uint32_t)(brow * 80 + kcol * 2);
                ldsm4(bh[nt], bHiT + off);
                ldsm4(bl[nt], bLoT + off);
            }
            #pragma unroll
            for (int mt = 0; mt < 4; mt++)
                #pragma unroll
                for (int nt = 0; nt < 2; nt++)
                    #pragma unroll
                    for (int g = 0; g < 2; g++) {
                        int j = nt * 2 + g;
                        mma_bf16(acc[mt][j], ah[mt], bh[nt][g * 2], bh[nt][g * 2 + 1]);
                        mma_bf16(acc[mt][j], ah[mt], bl[nt][g * 2], bl[nt][g * 2 + 1]);
                        mma_bf16(acc[mt][j], al[mt], bh[nt][g * 2], bh[nt][g * 2 + 1]);
                    }
        }
        __syncthreads();
    }

    // ---- epilogue: d frag: thread holds (g,2c),(g,2c+1),(g+8,2c),(g+8,2c+1)
    const int g2 = lane >> 2;
    const int c2 = (lane & 3) * 2;
    #pragma unroll
    for (int mt = 0; mt < 4; mt++) {
        int row0 = rowBase + mBase + mt * 16 + g2;
        #pragma unroll
        for (int j = 0; j < 4; j++) {
            int col = colBase + nBase + j * 8 + c2;
            *reinterpret_cast<float2*>(C + (long)row0 * CDIM + col) =
                make_float2(acc[mt][j][0], acc[mt][j][1]);
            *reinterpret_cast<float2*>(C + (long)(row0 + 8) * CDIM + col) =
                make_float2(acc[mt][j][2], acc[mt][j][3]);
        }
    }
}

// ---------------------------------------------------------------------------
// Kernel 4: WKV scan (group-of-8 prefetch). Writes rwkv = sigmoid(r)*wkv as
// bf16 hi/lo into activation slot 0. Emits final aa/bb/pp.
// ---------------------------------------------------------------------------
__global__ __launch_bounds__(64)
void wkv_scan_kernel(const float* __restrict__ aa_in,
                     const float* __restrict__ bb_in,
                     const float* __restrict__ pp_in,
                     const float* __restrict__ time_first,
                     const float* __restrict__ time_decay,
                     float* __restrict__ aa_out,
                     float* __restrict__ bb_out,
                     float* __restrict__ pp_out)
{
    int g = blockIdx.x * 64 + threadIdx.x;       // 0 .. B*C-1
    if (g >= BDIM * CDIM) return;
    int b = g >> 10;
    int c = g & (CDIM - 1);

    float aa = aa_in[g], bb = bb_in[g], pp = pp_in[g];
    const float tf = time_first[c];
    const float td = time_decay[c];

    const long base = (long)b * TDIM * CDIM + c;
    const float* kp = g_kvr + 0L * ELEMS + base;
    const float* vp = g_kvr + 1L * ELEMS + base;
    const float* rp = g_kvr + 2L * ELEMS + base;
    __nv_bfloat16* ophi = g_ahi + 0L * ELEMS + base;
    __nv_bfloat16* oplo = g_alo + 0L * ELEMS + base;

    #define GRP 8
    for (int t0 = 0; t0 < TDIM; t0 += GRP) {
        float kq[GRP], vq[GRP], rq[GRP];
        #pragma unroll
        for (int u = 0; u < GRP; u++) {
            long off = (long)(t0 + u) * CDIM;
            kq[u] = kp[off];
            vq[u] = vp[off];
            rq[u] = rp[off];
        }
        #pragma unroll
        for (int u = 0; u < GRP; u++) {
            float kt = kq[u], vt = vq[u], rt = rq[u];
            float ww = tf + kt;
            float qq = fmaxf(pp, ww);
            float e1 = __expf(pp - qq);
            float e2 = __expf(ww - qq);
            float wkv = (e1 * aa + e2 * vt) / (e1 * bb + e2);

            float sig = 1.0f / (1.0f + __expf(-rt));
            float rwkv = sig * wkv;
            long off = (long)(t0 + u) * CDIM;
            __nv_bfloat16 h = __float2bfloat16(rwkv);
            ophi[off] = h;
            oplo[off] = __float2bfloat16(rwkv - __bfloat162float(h));

            float ww2 = pp + td;
            float qq2 = fmaxf(ww2, kt);
            float e1b = __expf(ww2 - qq2);
            float e2b = __expf(kt - qq2);
            aa = e1b * aa + e2b * vt;
            bb = e1b * bb + e2b;
            pp = qq2;
        }
    }
    #undef GRP

    aa_out[g] = aa;
    bb_out[g] = bb;
    pp_out[g] = pp;
}

// ---------------------------------------------------------------------------
// Launch
// ---------------------------------------------------------------------------
extern "C" void kernel_launch(void* const* d_in, const int* in_sizes, int n_in,
                              void* d_out, int out_size)
{
    const float* x       = (const float*)d_in[0];
    const float* last_x  = (const float*)d_in[1];
    const float* aa      = (const float*)d_in[2];
    const float* bb      = (const float*)d_in[3];
    const float* pp      = (const float*)d_in[4];
    const float* tmk     = (const float*)d_in[5];
    const float* tmv     = (const float*)d_in[6];
    const float* tmr     = (const float*)d_in[7];
    const float* tfirst  = (const float*)d_in[8];
    const float* tdecay  = (const float*)d_in[9];
    const float* Wk      = (const float*)d_in[10];
    const float* Wv      = (const float*)d_in[11];
    const float* Wr      = (const float*)d_in[12];
    const float* Wo      = (const float*)d_in[13];

    float* out       = (float*)d_out;
    float* out_lastx = out + (long)ELEMS;
    float* out_aa    = out_lastx + BDIM * CDIM;
    float* out_bb    = out_aa    + BDIM * CDIM;
    float* out_pp    = out_bb    + BDIM * CDIM;

    __nv_bfloat16 *p_ahi, *p_alo, *p_wthi, *p_wtlo;
    float *p_kvr;
    cudaGetSymbolAddress((void**)&p_ahi,  g_ahi);
    cudaGetSymbolAddress((void**)&p_alo,  g_alo);
    cudaGetSymbolAddress((void**)&p_wthi, g_wthi);
    cudaGetSymbolAddress((void**)&p_wtlo, g_wtlo);
    cudaGetSymbolAddress((void**)&p_kvr,  g_kvr);

    cudaFuncSetAttribute(gemm_mma, cudaFuncAttributeMaxDynamicSharedMemorySize,
                         GEMM_SMEM);

    // 1) token-shift mixes -> bf16 hi/lo
    mix_kernel<<<ELEMS / 256, 256>>>(x, last_x, tmk, tmv, tmr, out_lastx);

    // 2) weight transpose + split (tiled, coalesced both sides)
    dim3 wgrid(CDIM / 32, CDIM / 32, 4);
    wconv_kernel<<<wgrid, 256>>>(Wk, Wv, Wr, Wo);

    // 3) three projection GEMMs (HMMA), one batched z-launch
    dim3 grid3(CDIM / 128, MTOT / 128, 3);
    gemm_mma<<<grid3, 256, GEMM_SMEM>>>(p_ahi, p_alo, p_wthi, p_wtlo, p_kvr,
                                        (long)ELEMS, (long)CDIM * CDIM,
                                        (long)ELEMS);

    // 4) WKV scan + fused sigmoid(r)*wkv -> bf16 hi/lo (slot 0)
    wkv_scan_kernel<<<(BDIM * CDIM) / 64, 64>>>(aa, bb, pp, tfirst, tdecay,
                                                out_aa, out_bb, out_pp);

    // 5) output projection: out = rwkv @ Wo (weight slot 3)
    dim3 grid1(CDIM / 128, MTOT / 128, 1);
    gemm_mma<<<grid1, 256, GEMM_SMEM>>>(p_ahi, p_alo,
                                        p_wthi + 3L * CDIM * CDIM,
                                        p_wtlo + 3L * CDIM * CDIM,
                                        out, 0L, 0L, 0L);
}

// round 14
// speedup vs baseline: 2.5317x; 1.0635x over previous
#include <cuda_runtime.h>
#include <cuda_bf16.h>
#include <cstdint>

#define BDIM 8
#define TDIM 2048
#define CDIM 1024
#define MTOT (BDIM * TDIM)          // 16384
#define ELEMS (MTOT * CDIM)         // 16,777,216

// ---------------------------------------------------------------------------
// Scratch (static device arrays — no allocation allowed)
// ---------------------------------------------------------------------------
// bf16 hi/lo split activations: slot 0=xk (reused as rwkv), 1=xv, 2=xr
__device__ __align__(128) __nv_bfloat16 g_ahi[3L * ELEMS];
__device__ __align__(128) __nv_bfloat16 g_alo[3L * ELEMS];
// fp32 GEMM outputs: slot 0=k, 1=v, 2=r_pre
__device__ __align__(128) float g_kvr[3L * ELEMS];
// transposed bf16 hi/lo weights: slot 0=Wk,1=Wv,2=Wr,3=Wo ; layout [n][k]
__device__ __align__(128) __nv_bfloat16 g_wthi[4L * CDIM * CDIM];
__device__ __align__(128) __nv_bfloat16 g_wtlo[4L * CDIM * CDIM];

// ---------------------------------------------------------------------------
// PTX helpers — baseline sm_80+ ISA only (harness targets plain sm_103!)
// ---------------------------------------------------------------------------
__device__ __forceinline__ uint32_t smem_u32(const void* p) {
    uint32_t a;
    asm("{ .reg .u64 t; cvta.to.shared.u64 t, %1; cvt.u32.u64 %0, t; }"
        : "=r"(a) : "l"(p));
    return a;
}
__device__ __forceinline__ void cp16(uint32_t s, const void* g) {
    asm volatile("cp.async.cg.shared.global [%0], [%1], 16;"
                 :: "r"(s), "l"(g) : "memory");
}
#define CP_COMMIT() asm volatile("cp.async.commit_group;" ::: "memory")
#define CP_WAIT(n)  asm volatile("cp.async.wait_group %0;" :: "n"(n) : "memory")

__device__ __forceinline__ void ldsm4(uint32_t* r, uint32_t addr) {
    asm volatile("ldmatrix.sync.aligned.m8n8.x4.shared.b16 {%0,%1,%2,%3}, [%4];"
                 : "=r"(r[0]), "=r"(r[1]), "=r"(r[2]), "=r"(r[3]) : "r"(addr));
}
__device__ __forceinline__ void mma_bf16(float* d, const uint32_t* a,
                                         uint32_t b0, uint32_t b1) {
    asm volatile(
        "mma.sync.aligned.m16n8k16.row.col.f32.bf16.bf16.f32 "
        "{%0,%1,%2,%3}, {%4,%5,%6,%7}, {%8,%9}, {%0,%1,%2,%3};"
        : "+f"(d[0]), "+f"(d[1]), "+f"(d[2]), "+f"(d[3])
        : "r"(a[0]), "r"(a[1]), "r"(a[2]), "r"(a[3]), "r"(b0), "r"(b1));
}

// ---------------------------------------------------------------------------
// Kernel 1: token-shift mix -> hi/lo bf16 activation arrays + last_x
// ---------------------------------------------------------------------------
__device__ __forceinline__ void split_store(__nv_bfloat16* hi, __nv_bfloat16* lo,
                                            long idx, float v) {
    __nv_bfloat16 h = __float2bfloat16(v);
    float rem = v - __bfloat162float(h);
    hi[idx] = h;
    lo[idx] = __float2bfloat16(rem);
}

__global__ __launch_bounds__(256)
void mix_kernel(const float* __restrict__ x,
                const float* __restrict__ last_x,
                const float* __restrict__ tmk,
                const float* __restrict__ tmv,
                const float* __restrict__ tmr,
                float* __restrict__ out_lastx)
{
    long idx = (long)blockIdx.x * 256 + threadIdx.x;
    if (idx >= ELEMS) return;
    int c = (int)(idx & (CDIM - 1));
    long m = idx >> 10;
    int t = (int)(m & (TDIM - 1));
    int b = (int)(m >> 11);

    float xc = x[idx];
    float xp = (t == 0) ? last_x[b * CDIM + c] : x[idx - CDIM];
    float d = xc - xp;

    split_store(g_ahi + 0L * ELEMS, g_alo + 0L * ELEMS, idx, fmaf(tmk[c], d, xp));
    split_store(g_ahi + 1L * ELEMS, g_alo + 1L * ELEMS, idx, fmaf(tmv[c], d, xp));
    split_store(g_ahi + 2L * ELEMS, g_alo + 2L * ELEMS, idx, fmaf(tmr[c], d, xp));

    if (t == TDIM - 1) out_lastx[b * CDIM + c] = xc;
}

// ---------------------------------------------------------------------------
// Kernel 2: tiled weight transpose + hi/lo bf16 split. wt[n][k] = W[k][n].
// ---------------------------------------------------------------------------
__global__ __launch_bounds__(256)
void wconv_kernel(const float* __restrict__ W0, const float* __restrict__ W1,
                  const float* __restrict__ W2, const float* __restrict__ W3)
{
    __shared__ float tile[32][33];
    const int w = blockIdx.z;
    const float* W = (w == 0) ? W0 : (w == 1) ? W1 : (w == 2) ? W2 : W3;

    const int k0 = blockIdx.y * 32;
    const int n0 = blockIdx.x * 32;
    const int tx = threadIdx.x & 31;
    const int ty = threadIdx.x >> 5;

    #pragma unroll
    for (int j = 0; j < 4; j++) {
        int k = ty + j * 8;
        tile[k][tx] = W[(long)(k0 + k) * CDIM + n0 + tx];
    }
    __syncthreads();

    long base = (long)w * CDIM * CDIM;
    #pragma unroll
    for (int j = 0; j < 4; j++) {
        int n = ty + j * 8;
        float v = tile[tx][n];
        long o = base + (long)(n0 + n) * CDIM + k0 + tx;
        __nv_bfloat16 h = __float2bfloat16(v);
        g_wthi[o] = h;
        g_wtlo[o] = __float2bfloat16(v - __bfloat162float(h));
    }
}

// ---------------------------------------------------------------------------
// Kernel 3: bf16 split GEMM via mma.sync (HMMA). (unchanged, verified pass)
// ---------------------------------------------------------------------------
#define BKG   32
#define TSTR  10240     // tile bytes: 128 rows x 80B stride
#define STAGE 40960     // 4 tiles per stage
#define GEMM_SMEM (2 * STAGE)   // 81920

__global__ __launch_bounds__(256, 1)
void gemm_mma(const __nv_bfloat16* __restrict__ AhiB,
              const __nv_bfloat16* __restrict__ AloB,
              const __nv_bfloat16* __restrict__ WhiB,
              const __nv_bfloat16* __restrict__ WloB,
              float* __restrict__ CB,
              long aStride, long wStride, long cStride)
{
    extern __shared__ char dynsmem[];
    const int z = blockIdx.z;
    const __nv_bfloat16* Ahi = AhiB + (long)z * aStride;
    const __nv_bfloat16* Alo = AloB + (long)z * aStride;
    const __nv_bfloat16* Whi = WhiB + (long)z * wStride;
    const __nv_bfloat16* Wlo = WloB + (long)z * wStride;
    float* C = CB + (long)z * cStride;

    const int tid  = threadIdx.x;
    const int wid  = tid >> 5;
    const int lane = tid & 31;
    const int rowBase = blockIdx.y * 128;
    const int colBase = blockIdx.x * 128;
    const int mBase = (wid >> 2) * 64;
    const int nBase = (wid & 3) * 32;

    const uint32_t sb = smem_u32(dynsmem);

    float acc[4][4][4];
    #pragma unroll
    for (int a = 0; a < 4; a++)
        #pragma unroll
        for (int b = 0; b < 4; b++)
            #pragma unroll
            for (int c = 0; c < 4; c++) acc[a][b][c] = 0.f;

    auto copyStage = [&](int stage, int kc) {
        uint32_t sbase = sb + stage * STAGE;
        #pragma unroll
        for (int j = 0; j < 8; j++) {
            int idx = j * 256 + tid;
            int tile = idx >> 9;
            int ci   = idx & 511;
            int row  = ci >> 2;
            int c4   = ci & 3;
            uint32_t soff = sbase + tile * TSTR + row * 80 + c4 * 16;
            const __nv_bfloat16* gp;
            if (tile == 0)      gp = Ahi + (long)(rowBase + row) * CDIM + kc + c4 * 8;
            else if (tile == 1) gp = Alo + (long)(rowBase + row) * CDIM + kc + c4 * 8;
            else if (tile == 2) gp = Whi + (long)(colBase + row) * CDIM + kc + c4 * 8;
            else                gp = Wlo + (long)(colBase + row) * CDIM + kc + c4 * 8;
            cp16(soff, gp);
        }
    };

    copyStage(0, 0);
    CP_COMMIT();

    const int S = CDIM / BKG;
    const int sub = lane >> 3;
    const int r8  = lane & 7;

    for (int s = 0; s < S; s++) {
        if (s + 1 < S) { copyStage((s + 1) & 1, (s + 1) * BKG); CP_COMMIT(); CP_WAIT(1); }
        else           { CP_WAIT(0); }
        __syncthreads();

        uint32_t st   = sb + (s & 1) * STAGE;
        uint32_t aHiT = st;
        uint32_t aLoT = st + TSTR;
        uint32_t bHiT = st + 2 * TSTR;
        uint32_t bLoT = st + 3 * TSTR;

        #pragma unroll
        for (int k16 = 0; k16 < BKG; k16 += 16) {
            uint32_t ah[4][4], al[4][4], bh[2][4], bl[2][4];
            #pragma unroll
            for (int mt = 0; mt < 4; mt++) {
                int arow = mBase + mt * 16 + (sub & 1) * 8 + r8;
                int kcol = k16 + (sub >> 1) * 8;
                uint32_t off = (uint32_t)(arow * 80 + kcol * 2);
                ldsm4(ah[mt], aHiT + off);
                ldsm4(al[mt], aLoT + off);
            }
            #pragma unroll
            for (int nt = 0; nt < 2; nt++) {
                int brow = nBase + nt * 16 + (sub >> 1) * 8 + r8;
                int kcol = k16 + (sub & 1) * 8;
                uint32_t off = (uint32_t)(brow * 80 + kcol * 2);
                ldsm4(bh[nt], bHiT + off);
                ldsm4(bl[nt], bLoT + off);
            }
            #pragma unroll
            for (int mt = 0; mt < 4; mt++)
                #pragma unroll
                for (int nt = 0; nt < 2; nt++)
                    #pragma unroll
                    for (int g = 0; g < 2; g++) {
                        int j = nt * 2 + g;
                        mma_bf16(acc[mt][j], ah[mt], bh[nt][g * 2], bh[nt][g * 2 + 1]);
                        mma_bf16(acc[mt][j], ah[mt], bl[nt][g * 2], bl[nt][g * 2 + 1]);
                        mma_bf16(acc[mt][j], al[mt], bh[nt][g * 2], bh[nt][g * 2 + 1]);
                    }
        }
        __syncthreads();
    }

    const int g2 = lane >> 2;
    const int c2 = (lane & 3) * 2;
    #pragma unroll
    for (int mt = 0; mt < 4; mt++) {
        int row0 = rowBase + mBase + mt * 16 + g2;
        #pragma unroll
        for (int j = 0; j < 4; j++) {
            int col = colBase + nBase + j * 8 + c2;
            *reinterpret_cast<float2*>(C + (long)row0 * CDIM + col) =
                make_float2(acc[mt][j][0], acc[mt][j][1]);
            *reinterpret_cast<float2*>(C + (long)(row0 + 8) * CDIM + col) =
                make_float2(acc[mt][j][2], acc[mt][j][3]);
        }
    }
}

// ---------------------------------------------------------------------------
// Kernel 4: WKV scan — cp.async double-buffered smem pipeline.
// 64 threads/block = 64 consecutive channels (same batch b since 64|1024).
// Per group of 8 timesteps: 24 rows x 256B stream into smem while the
// previous group computes. Registers stay low; MLP lives in the cp.async
// queue, so DRAM latency is hidden behind compute.
// ---------------------------------------------------------------------------
#define GRP 8

__global__ __launch_bounds__(64)
void wkv_scan_kernel(const float* __restrict__ aa_in,
                     const float* __restrict__ bb_in,
                     const float* __restrict__ pp_in,
                     const float* __restrict__ time_first,
                     const float* __restrict__ time_decay,
                     float* __restrict__ aa_out,
                     float* __restrict__ bb_out,
                     float* __restrict__ pp_out)
{
    __shared__ __align__(16) float sbuf[2][3][GRP][64];

    const int tid = threadIdx.x;
    const int g = blockIdx.x * 64 + tid;          // 0 .. B*C-1
    const int b = (blockIdx.x * 64) >> 10;        // all 64 lanes share b
    const int c0 = (blockIdx.x * 64) & (CDIM - 1);
    const int c = c0 + tid;

    float aa = aa_in[g], bb = bb_in[g], pp = pp_in[g];
    const float tf = time_first[c];
    const float td = time_decay[c];

    const long rowb = (long)b * TDIM * CDIM + c0; // block-row base (chan 0)
    const long base = rowb + tid;                 // this thread's channel
    __nv_bfloat16* ophi = g_ahi + 0L * ELEMS + base;
    __nv_bfloat16* oplo = g_alo + 0L * ELEMS + base;

    // fill stage st with timesteps [t0, t0+GRP): 24 rows x 16 chunks = 384
    // cp16 ops, 6 per thread.
    auto fill = [&](int st, int t0) {
        #pragma unroll
        for (int j = 0; j < 6; j++) {
            int idx = j * 64 + tid;      // 0..383
            int row = idx >> 4;          // 0..23
            int ch  = idx & 15;          // 16B chunk within 256B row
            int arr = row >> 3;          // 0=k, 1=v, 2=r
            int u   = row & 7;
            const float* src = g_kvr + (long)arr * ELEMS + rowb
                             + (long)(t0 + u) * CDIM + ch * 4;
            cp16(smem_u32(&sbuf[st][arr][u][ch * 4]), src);
        }
        CP_COMMIT();
    };

    fill(0, 0);

    const int NG = TDIM / GRP;   // 256
    for (int grp = 0; grp < NG; grp++) {
        if (grp + 1 < NG) { fill((grp + 1) & 1, (grp + 1) * GRP); CP_WAIT(1); }
        else              { CP_WAIT(0); }
        __syncthreads();

        const int st = grp & 1;
        #pragma unroll
        for (int u = 0; u < GRP; u++) {
            float kt = sbuf[st][0][u][tid];
            float vt = sbuf[st][1][u][tid];
            float rt = sbuf[st][2][u][tid];

            float ww = tf + kt;
            float qq = fmaxf(pp, ww);
            float e1 = __expf(pp - qq);
            float e2 = __expf(ww - qq);
            float wkv = (e1 * aa + e2 * vt) / (e1 * bb + e2);

            float sig = 1.0f / (1.0f + __expf(-rt));
            float rwkv = sig * wkv;
            long off = (long)(grp * GRP + u) * CDIM;
            __nv_bfloat16 h = __float2bfloat16(rwkv);
            ophi[off] = h;
            oplo[off] = __float2bfloat16(rwkv - __bfloat162float(h));

            float ww2 = pp + td;
            float qq2 = fmaxf(ww2, kt);
            float e1b = __expf(ww2 - qq2);
            float e2b = __expf(kt - qq2);
            aa = e1b * aa + e2b * vt;
            bb = e1b * bb + e2b;
            pp = qq2;
        }
        __syncthreads();   // protect buffer (grp&1) before refill at grp+2
    }

    aa_out[g] = aa;
    bb_out[g] = bb;
    pp_out[g] = pp;
}

// ---------------------------------------------------------------------------
// Launch
// ---------------------------------------------------------------------------
extern "C" void kernel_launch(void* const* d_in, const int* in_sizes, int n_in,
                              void* d_out, int out_size)
{
    const float* x       = (const float*)d_in[0];
    const float* last_x  = (const float*)d_in[1];
    const float* aa      = (const float*)d_in[2];
    const float* bb      = (const float*)d_in[3];
    const float* pp      = (const float*)d_in[4];
    const float* tmk     = (const float*)d_in[5];
    const float* tmv     = (const float*)d_in[6];
    const float* tmr     = (const float*)d_in[7];
    const float* tfirst  = (const float*)d_in[8];
    const float* tdecay  = (const float*)d_in[9];
    const float* Wk      = (const float*)d_in[10];
    const float* Wv      = (const float*)d_in[11];
    const float* Wr      = (const float*)d_in[12];
    const float* Wo      = (const float*)d_in[13];

    float* out       = (float*)d_out;
    float* out_lastx = out + (long)ELEMS;
    float* out_aa    = out_lastx + BDIM * CDIM;
    float* out_bb    = out_aa    + BDIM * CDIM;
    float* out_pp    = out_bb    + BDIM * CDIM;

    __nv_bfloat16 *p_ahi, *p_alo, *p_wthi, *p_wtlo;
    float *p_kvr;
    cudaGetSymbolAddress((void**)&p_ahi,  g_ahi);
    cudaGetSymbolAddress((void**)&p_alo,  g_alo);
    cudaGetSymbolAddress((void**)&p_wthi, g_wthi);
    cudaGetSymbolAddress((void**)&p_wtlo, g_wtlo);
    cudaGetSymbolAddress((void**)&p_kvr,  g_kvr);

    cudaFuncSetAttribute(gemm_mma, cudaFuncAttributeMaxDynamicSharedMemorySize,
                         GEMM_SMEM);

    // 1) token-shift mixes -> bf16 hi/lo
    mix_kernel<<<ELEMS / 256, 256>>>(x, last_x, tmk, tmv, tmr, out_lastx);

    // 2) weight transpose + split (tiled, coalesced both sides)
    dim3 wgrid(CDIM / 32, CDIM / 32, 4);
    wconv_kernel<<<wgrid, 256>>>(Wk, Wv, Wr, Wo);

    // 3) three projection GEMMs (HMMA), one batched z-launch
    dim3 grid3(CDIM / 128, MTOT / 128, 3);
    gemm_mma<<<grid3, 256, GEMM_SMEM>>>(p_ahi, p_alo, p_wthi, p_wtlo, p_kvr,
                                        (long)ELEMS, (long)CDIM * CDIM,
                                        (long)ELEMS);

    // 4) WKV scan + fused sigmoid(r)*wkv -> bf16 hi/lo (slot 0)
    wkv_scan_kernel<<<(BDIM * CDIM) / 64, 64>>>(aa, bb, pp, tfirst, tdecay,
                                                out_aa, out_bb, out_pp);

    // 5) output projection: out = rwkv @ Wo (weight slot 3)
    dim3 grid1(CDIM / 128, MTOT / 128, 1);
    gemm_mma<<<grid1, 256, GEMM_SMEM>>>(p_ahi, p_alo,
                                        p_wthi + 3L * CDIM * CDIM,
                                        p_wtlo + 3L * CDIM * CDIM,
                                        out, 0L, 0L, 0L);
}